// round 3
// baseline (speedup 1.0000x reference)
#include <cuda_runtime.h>
#include <math.h>

#define S_LEN 2048
#define E_DIM 1024
#define NHEAD 8
#define DHEAD 128
#define EPS 1e-6f
#define SCALE 0.08838834764831845f  /* 1/sqrt(128) */

#define PQ 68    /* padded row length of transposed Q/K tiles (64 + 4) */
#define PV 132   /* padded row length of V tile (128 + 4) */
#define PP 68    /* padded row length of P tile (64 + 4) */

#define SMEM_BYTES ((DHEAD*PQ*2 + 64*PV + 64*PP) * 4)

// ---------------- scratch (device globals; no allocation allowed) --------------
__device__ float g_ipre[NHEAD * S_LEN];
__device__ float g_lsf [NHEAD * S_LEN];
__device__ float g_cum [NHEAD * S_LEN];
__device__ float g_g   [NHEAD * S_LEN];
__device__ float g_M   [NHEAD * S_LEN];

__device__ __forceinline__ float logsigf(float x) {
    // log(sigmoid(x)) = min(x,0) - log1p(exp(-|x|))
    return fminf(x, 0.0f) - log1pf(expf(-fabsf(x)));
}

// ---------------- kernel 1: gate preactivations --------------------------------
// i_pre[h][s] = concat(q,k,v)[s] . Wi[:,h] + bi[h]
// lsf[h][s]   = log_sigmoid( concat . Wf[:,h] + bf[h] )
// 128 threads = 4 warps, 2 rows/warp, 8 rows/block, 256 blocks.
__global__ void gates_kernel(const float* __restrict__ q, const float* __restrict__ k,
                             const float* __restrict__ v,
                             const float* __restrict__ Wi, const float* __restrict__ bi,
                             const float* __restrict__ Wf, const float* __restrict__ bf)
{
    int warp = threadIdx.x >> 5, lane = threadIdx.x & 31;
    int s0 = blockIdx.x * 8 + warp * 2;

    float acc[2][16];
#pragma unroll
    for (int r = 0; r < 2; r++)
#pragma unroll
        for (int j = 0; j < 16; j++) acc[r][j] = 0.f;

    for (int e = lane; e < 3 * E_DIM; e += 32) {
        float w[16];
#pragma unroll
        for (int j = 0; j < 8; j++) { w[j] = Wi[e * 8 + j]; w[8 + j] = Wf[e * 8 + j]; }
        float x0, x1;
        if (e < E_DIM)            { x0 = q[(s0)*E_DIM + e];            x1 = q[(s0+1)*E_DIM + e]; }
        else if (e < 2 * E_DIM)   { x0 = k[(s0)*E_DIM + e - E_DIM];    x1 = k[(s0+1)*E_DIM + e - E_DIM]; }
        else                      { x0 = v[(s0)*E_DIM + e - 2*E_DIM];  x1 = v[(s0+1)*E_DIM + e - 2*E_DIM]; }
#pragma unroll
        for (int j = 0; j < 16; j++) { acc[0][j] += x0 * w[j]; acc[1][j] += x1 * w[j]; }
    }

#pragma unroll
    for (int r = 0; r < 2; r++) {
#pragma unroll
        for (int j = 0; j < 16; j++) {
            float val = acc[r][j];
#pragma unroll
            for (int o = 16; o > 0; o >>= 1) val += __shfl_down_sync(0xffffffffu, val, o);
            if (lane == 0) {
                int s = s0 + r;
                if (j < 8) g_ipre[j * S_LEN + s] = val + bi[j];
                else       g_lsf[(j - 8) * S_LEN + s] = logsigf(val + bf[j - 8]);
            }
        }
    }
}

// ---------------- kernel 2: per-head scans --------------------------------------
// cum = inclusive cumsum(lsf); g = ipre - cum; M = running max(g).
// One block per head, 256 threads x 8 elements.
__global__ void scan_kernel()
{
    int h = blockIdx.x;
    int t = threadIdx.x;
    __shared__ float sh[256];
    const int SEQ = S_LEN / 256;  // 8

    float vals[8];
    float loc = 0.f;
#pragma unroll
    for (int j = 0; j < SEQ; j++) { vals[j] = g_lsf[h * S_LEN + t * SEQ + j]; loc += vals[j]; }
    sh[t] = loc; __syncthreads();
    for (int off = 1; off < 256; off <<= 1) {
        float x = sh[t];
        float y = (t >= off) ? sh[t - off] : 0.f;
        __syncthreads();
        sh[t] = x + y;
        __syncthreads();
    }
    float c = (t > 0) ? sh[t - 1] : 0.f;

    float gv[8];
    float lm = -INFINITY;
#pragma unroll
    for (int j = 0; j < SEQ; j++) {
        c += vals[j];
        g_cum[h * S_LEN + t * SEQ + j] = c;
        float gg = g_ipre[h * S_LEN + t * SEQ + j] - c;
        gv[j] = gg;
        g_g[h * S_LEN + t * SEQ + j] = gg;
        lm = fmaxf(lm, gg);
    }
    __syncthreads();
    sh[t] = lm; __syncthreads();
    for (int off = 1; off < 256; off <<= 1) {
        float x = sh[t];
        float y = (t >= off) ? sh[t - off] : -INFINITY;
        __syncthreads();
        sh[t] = fmaxf(x, y);
        __syncthreads();
    }
    float m = (t > 0) ? sh[t - 1] : -INFINITY;
#pragma unroll
    for (int j = 0; j < SEQ; j++) {
        m = fmaxf(m, gv[j]);
        g_M[h * S_LEN + t * SEQ + j] = m;
    }
}

// ---------------- kernel 3: fused causal decay-attention + normalize + LN -------
// One block = (head h, 64-row query tile). 128 threads.
// S-phase thread tile: 8 rows x 4 cols of the 64x64 S tile.
// O-phase thread tile: 8 rows x 8 cols of the 64x128 output tile.
__global__ __launch_bounds__(128, 1)
void mlstm_main_kernel(const float* __restrict__ q, const float* __restrict__ k,
                       const float* __restrict__ v, const float* __restrict__ lnsc,
                       float* __restrict__ out)
{
    extern __shared__ float smem[];
    float* Qt = smem;               // [DHEAD][PQ]  (transposed, swizzled)
    float* Kt = Qt + DHEAD * PQ;    // [DHEAD][PQ]
    float* Vs = Kt + DHEAD * PQ;    // [64][PV]     (row-major)
    float* Ps = Vs + 64 * PV;       // [64][PP]     (swizzled)
    __shared__ float gsh[64], marr[64], nbarr[64];
    __shared__ float red1[64][17], red2[64][17];

    int t  = threadIdx.x;
    int h  = blockIdx.y;
    int it = (gridDim.x - 1) - blockIdx.x;   // big tiles first for load balance
    int i0 = it * 64;
    int sy = t >> 4;   // 0..7
    int sx = t & 15;   // 0..15

    if (t < 64) {
        float mm = g_M[h * S_LEN + i0 + t];
        marr[t]  = mm;
        nbarr[t] = __expf(-(g_cum[h * S_LEN + i0 + t] + mm));
    }

    // Load Q tile transposed with swizzle: logical Qt[d][r] at phys r^(((d>>2)&7)<<2)
    {
        const float* qp = q + (size_t)i0 * E_DIM + h * DHEAD;
        for (int iter = 0; iter < 16; iter++) {
            int idx = iter * 128 + t;       // 2048 float4s
            int row = idx >> 5;             // q-row 0..63
            int c4  = (idx & 31) * 4;       // d base
            float4 qv = *(const float4*)(qp + (size_t)row * E_DIM + c4);
            float vv[4] = {qv.x, qv.y, qv.z, qv.w};
#pragma unroll
            for (int qq = 0; qq < 4; qq++) {
                int d = c4 + qq;
                int swz = ((d >> 2) & 7) << 2;
                Qt[d * PQ + (row ^ swz)] = vv[qq];
            }
        }
    }

    float o[8][8];
#pragma unroll
    for (int i = 0; i < 8; i++)
#pragma unroll
        for (int c = 0; c < 8; c++) o[i][c] = 0.f;
    float rs[8];
#pragma unroll
    for (int i = 0; i < 8; i++) rs[i] = 0.f;

    for (int j0 = 0; j0 <= i0; j0 += 64) {
        __syncthreads();   // previous iter done with Kt/Vs/Ps
        {
            const float* kp = k + (size_t)j0 * E_DIM + h * DHEAD;
            const float* vp = v + (size_t)j0 * E_DIM + h * DHEAD;
            for (int iter = 0; iter < 16; iter++) {
                int idx = iter * 128 + t;
                int row = idx >> 5;
                int c4  = (idx & 31) * 4;
                float4 kv = *(const float4*)(kp + (size_t)row * E_DIM + c4);
                float4 vv = *(const float4*)(vp + (size_t)row * E_DIM + c4);
                float ka[4] = {kv.x, kv.y, kv.z, kv.w};
#pragma unroll
                for (int qq = 0; qq < 4; qq++) {
                    int d = c4 + qq;
                    int swz = ((d >> 2) & 7) << 2;
                    Kt[d * PQ + (row ^ swz)] = ka[qq];
                }
                *(float4*)(Vs + row * PV + c4) = vv;
            }
            if (t < 64) gsh[t] = g_g[h * S_LEN + j0 + t];
        }
        __syncthreads();

        // ---- S = Q K^T (64x64), 8x4 per thread ----
        float acc[8][4];
#pragma unroll
        for (int i = 0; i < 8; i++)
#pragma unroll
            for (int j = 0; j < 4; j++) acc[i][j] = 0.f;

#pragma unroll 4
        for (int kk = 0; kk < DHEAD; kk++) {
            int swz = ((kk >> 2) & 7) << 2;
            const float* qrow = Qt + kk * PQ;
            const float* krow = Kt + kk * PQ;
            float4 a0 = *(const float4*)(qrow + ((sy * 8) ^ swz));
            float4 a1 = *(const float4*)(qrow + ((sy * 8 + 4) ^ swz));
            float4 b  = *(const float4*)(krow + ((sx * 4) ^ swz));
            float a[8]  = {a0.x, a0.y, a0.z, a0.w, a1.x, a1.y, a1.z, a1.w};
            float bb[4] = {b.x, b.y, b.z, b.w};
#pragma unroll
            for (int i = 0; i < 8; i++)
#pragma unroll
                for (int j = 0; j < 4; j++)
                    acc[i][j] += a[i] * bb[j];
        }

        // ---- P = S * scale * exp(g_j - M_i), causal mask, row sums ----
        bool diag = (j0 == i0);
#pragma unroll
        for (int i = 0; i < 8; i++) {
            int r = sy * 8 + i;
            float m = marr[r];
            float pv[4];
#pragma unroll
            for (int j = 0; j < 4; j++) {
                int c = sx * 4 + j;
                float val = acc[i][j] * SCALE * __expf(gsh[c] - m);
                if (diag && c > r) val = 0.f;
                rs[i] += val;
                pv[j] = val;
            }
            int swz = sy << 2;  // r>>3 == sy
            *(float4*)(Ps + r * PP + ((sx * 4) ^ swz)) =
                make_float4(pv[0], pv[1], pv[2], pv[3]);
        }
        __syncthreads();

        // ---- O += P V (64x128), 8x8 per thread ----
#pragma unroll 2
        for (int j = 0; j < 64; j++) {
            float a[8];
#pragma unroll
            for (int i = 0; i < 8; i++)
                a[i] = Ps[(sy * 8 + i) * PP + (j ^ (sy << 2))];
            float4 b0 = *(const float4*)(Vs + j * PV + sx * 8);
            float4 b1 = *(const float4*)(Vs + j * PV + sx * 8 + 4);
            float bb[8] = {b0.x, b0.y, b0.z, b0.w, b1.x, b1.y, b1.z, b1.w};
#pragma unroll
            for (int i = 0; i < 8; i++)
#pragma unroll
                for (int c = 0; c < 8; c++)
                    o[i][c] += a[i] * bb[c];
        }
    }

    // ---- epilogue: normalizer, then fused per-head LayerNorm ----
    __syncthreads();
#pragma unroll
    for (int i = 0; i < 8; i++) red1[sy * 8 + i][sx] = rs[i];
    __syncthreads();

    float sA[8], sB[8];
#pragma unroll
    for (int i = 0; i < 8; i++) {
        int r = sy * 8 + i;
        float rsum = 0.f;
#pragma unroll
        for (int x = 0; x < 16; x++) rsum += red1[r][x];
        float norm = fmaxf(fabsf(rsum), nbarr[r]) + EPS;
        float inv = 1.0f / norm;
        float a1 = 0.f, a2 = 0.f;
#pragma unroll
        for (int c = 0; c < 8; c++) {
            float val = o[i][c] * inv;
            o[i][c] = val;
            a1 += val; a2 += val * val;
        }
        sA[i] = a1; sB[i] = a2;
    }
    __syncthreads();
#pragma unroll
    for (int i = 0; i < 8; i++) { red1[sy * 8 + i][sx] = sA[i]; red2[sy * 8 + i][sx] = sB[i]; }
    __syncthreads();

#pragma unroll
    for (int i = 0; i < 8; i++) {
        int r = sy * 8 + i;
        float m1 = 0.f, m2 = 0.f;
#pragma unroll
        for (int x = 0; x < 16; x++) { m1 += red1[r][x]; m2 += red2[r][x]; }
        float mu   = m1 * (1.0f / DHEAD);
        float var  = m2 * (1.0f / DHEAD) - mu * mu;
        float rstd = rsqrtf(var + EPS);
        float res[8];
#pragma unroll
        for (int c = 0; c < 8; c++) {
            int d = sx * 8 + c;
            res[c] = (o[i][c] - mu) * rstd * lnsc[h * DHEAD + d];
        }
        float4* op = (float4*)(out + (size_t)(i0 + r) * E_DIM + h * DHEAD + sx * 8);
        op[0] = make_float4(res[0], res[1], res[2], res[3]);
        op[1] = make_float4(res[4], res[5], res[6], res[7]);
    }
}

// ---------------- launch --------------------------------------------------------
extern "C" void kernel_launch(void* const* d_in, const int* in_sizes, int n_in,
                              void* d_out, int out_size)
{
    const float* q    = (const float*)d_in[0];
    const float* k    = (const float*)d_in[1];
    const float* v    = (const float*)d_in[2];
    const float* Wi   = (const float*)d_in[3];
    const float* bi   = (const float*)d_in[4];
    const float* Wf   = (const float*)d_in[5];
    const float* bf   = (const float*)d_in[6];
    const float* lnsc = (const float*)d_in[7];
    float* out = (float*)d_out;

    cudaFuncSetAttribute(mlstm_main_kernel,
                         cudaFuncAttributeMaxDynamicSharedMemorySize, SMEM_BYTES);

    gates_kernel<<<256, 128>>>(q, k, v, Wi, bi, Wf, bf);
    scan_kernel<<<NHEAD, 256>>>();
    dim3 grid(32, NHEAD);
    mlstm_main_kernel<<<grid, 128, SMEM_BYTES>>>(q, k, v, lnsc, out);
}

// round 4
// speedup vs baseline: 1.0080x; 1.0080x over previous
#include <cuda_runtime.h>
#include <math.h>

#define S_LEN 2048
#define E_DIM 1024
#define NHEAD 8
#define DHEAD 128
#define EPS 1e-6f
#define SCALE 0.08838834764831845f  /* 1/sqrt(128) */

#define PQ 68    /* padded row length of transposed Q/K tiles (64 + 4) */
#define PV 132   /* padded row length of V tile (128 + 4) */
#define PP 68    /* padded row length of P tile (64 + 4) */

#define SMEM_BYTES ((DHEAD*PQ*2 + 64*PV + 64*PP) * 4)

// ---------------- scratch (device globals; no allocation allowed) --------------
__device__ float g_parti[3][NHEAD * S_LEN];   // partial i-gate preacts per e-chunk
__device__ float g_partf[3][NHEAD * S_LEN];   // partial f-gate preacts per e-chunk
__device__ float g_cum [NHEAD * S_LEN];
__device__ float g_g   [NHEAD * S_LEN];
__device__ float g_M   [NHEAD * S_LEN];

__device__ __forceinline__ float logsigf(float x) {
    // log(sigmoid(x)) = min(x,0) - log1p(exp(-|x|))
    return fminf(x, 0.0f) - log1pf(expf(-fabsf(x)));
}

// ---------------- kernel 1: gate preactivations (partial sums) ------------------
// grid (128, 3): blockIdx.x = 16-row group, blockIdx.y = e-chunk (0=q,1=k,2=v).
// 128 threads = 4 warps x 4 rows. float4 weight/x loads (dense L1 wavefronts).
// Deterministic: each block writes its own partial slot; no atomics.
__global__ __launch_bounds__(128)
void gates_kernel(const float* __restrict__ q, const float* __restrict__ k,
                  const float* __restrict__ v,
                  const float* __restrict__ Wi, const float* __restrict__ Wf)
{
    int warp = threadIdx.x >> 5, lane = threadIdx.x & 31;
    int chunk = blockIdx.y;
    int s0 = blockIdx.x * 16 + warp * 4;

    const float* src = (chunk == 0) ? q : ((chunk == 1) ? k : v);
    const float* W0 = Wi + (size_t)chunk * 1024 * 8;
    const float* W1 = Wf + (size_t)chunk * 1024 * 8;

    float acc[4][16];
#pragma unroll
    for (int r = 0; r < 4; r++)
#pragma unroll
        for (int g = 0; g < 16; g++) acc[r][g] = 0.f;

#pragma unroll 2
    for (int it = 0; it < 8; it++) {
        int e = it * 128 + lane * 4;
        float xv[4][4];
#pragma unroll
        for (int r = 0; r < 4; r++) {
            float4 xq = *(const float4*)(src + (size_t)(s0 + r) * E_DIM + e);
            xv[r][0] = xq.x; xv[r][1] = xq.y; xv[r][2] = xq.z; xv[r][3] = xq.w;
        }
#pragma unroll
        for (int s = 0; s < 4; s++) {
            float4 wi0 = *(const float4*)(W0 + (size_t)(e + s) * 8);
            float4 wi1 = *(const float4*)(W0 + (size_t)(e + s) * 8 + 4);
            float4 wf0 = *(const float4*)(W1 + (size_t)(e + s) * 8);
            float4 wf1 = *(const float4*)(W1 + (size_t)(e + s) * 8 + 4);
            float w[16] = {wi0.x, wi0.y, wi0.z, wi0.w, wi1.x, wi1.y, wi1.z, wi1.w,
                           wf0.x, wf0.y, wf0.z, wf0.w, wf1.x, wf1.y, wf1.z, wf1.w};
#pragma unroll
            for (int r = 0; r < 4; r++)
#pragma unroll
                for (int g = 0; g < 16; g++)
                    acc[r][g] += xv[r][s] * w[g];
        }
    }

    // full butterfly reduce across the 32 lanes (every lane ends with the sum)
#pragma unroll
    for (int r = 0; r < 4; r++)
#pragma unroll
        for (int g = 0; g < 16; g++) {
#pragma unroll
            for (int o = 16; o > 0; o >>= 1)
                acc[r][g] += __shfl_xor_sync(0xffffffffu, acc[r][g], o);
        }

    // lane g writes gate g for all 4 rows (static register indexing)
#pragma unroll
    for (int g = 0; g < 16; g++) {
        if (lane == g) {
#pragma unroll
            for (int r = 0; r < 4; r++) {
                int s = s0 + r;
                if (g < 8) g_parti[chunk][g * S_LEN + s]       = acc[r][g];
                else       g_partf[chunk][(g - 8) * S_LEN + s] = acc[r][g];
            }
        }
    }
}

// ---------------- kernel 2: finalize gates + per-head scans ---------------------
// cum = inclusive cumsum(logsig(f_pre)); g = i_pre - cum; M = running max(g).
__global__ void scan_kernel(const float* __restrict__ bi, const float* __restrict__ bf)
{
    int h = blockIdx.x;
    int t = threadIdx.x;
    __shared__ float sh[256];
    const int SEQ = S_LEN / 256;  // 8

    float vals[8], iv[8];
    float loc = 0.f;
    float bih = bi[h], bfh = bf[h];
#pragma unroll
    for (int j = 0; j < SEQ; j++) {
        int s = t * SEQ + j;
        int idx = h * S_LEN + s;
        float fpre = g_partf[0][idx] + g_partf[1][idx] + g_partf[2][idx] + bfh;
        iv[j] = g_parti[0][idx] + g_parti[1][idx] + g_parti[2][idx] + bih;
        vals[j] = logsigf(fpre);
        loc += vals[j];
    }
    sh[t] = loc; __syncthreads();
    for (int off = 1; off < 256; off <<= 1) {
        float x = sh[t];
        float y = (t >= off) ? sh[t - off] : 0.f;
        __syncthreads();
        sh[t] = x + y;
        __syncthreads();
    }
    float c = (t > 0) ? sh[t - 1] : 0.f;

    float gv[8];
    float lm = -INFINITY;
#pragma unroll
    for (int j = 0; j < SEQ; j++) {
        c += vals[j];
        g_cum[h * S_LEN + t * SEQ + j] = c;
        float gg = iv[j] - c;
        gv[j] = gg;
        g_g[h * S_LEN + t * SEQ + j] = gg;
        lm = fmaxf(lm, gg);
    }
    __syncthreads();
    sh[t] = lm; __syncthreads();
    for (int off = 1; off < 256; off <<= 1) {
        float x = sh[t];
        float y = (t >= off) ? sh[t - off] : -INFINITY;
        __syncthreads();
        sh[t] = fmaxf(x, y);
        __syncthreads();
    }
    float m = (t > 0) ? sh[t - 1] : -INFINITY;
#pragma unroll
    for (int j = 0; j < SEQ; j++) {
        m = fmaxf(m, gv[j]);
        g_M[h * S_LEN + t * SEQ + j] = m;
    }
}

// ---------------- kernel 3: fused causal decay-attention + normalize + LN -------
// One block = (head h, 64-row query tile). 256 threads (2 warps/SMSP).
// S-phase thread tile: 4 rows x 4 cols of the 64x64 S tile.
// O-phase thread tile: 4 rows x 8 cols of the 64x128 output tile.
__global__ __launch_bounds__(256, 1)
void mlstm_main_kernel(const float* __restrict__ q, const float* __restrict__ k,
                       const float* __restrict__ v, const float* __restrict__ lnsc,
                       float* __restrict__ out)
{
    extern __shared__ float smem[];
    float* Qt = smem;               // [DHEAD][PQ]  (transposed, swizzled)
    float* Kt = Qt + DHEAD * PQ;    // [DHEAD][PQ]
    float* Vs = Kt + DHEAD * PQ;    // [64][PV]     (row-major)
    float* Ps = Vs + 64 * PV;       // [64][PP]     (swizzled)
    __shared__ float gsh[64], marr[64], nbarr[64];
    __shared__ float red1[64][17], red2[64][17];

    int t  = threadIdx.x;
    int h  = blockIdx.y;
    int it = (gridDim.x - 1) - blockIdx.x;   // big tiles first for load balance
    int i0 = it * 64;
    int tx = t & 15;    // 0..15
    int ty = t >> 4;    // 0..15

    if (t < 64) {
        float mm = g_M[h * S_LEN + i0 + t];
        marr[t]  = mm;
        nbarr[t] = __expf(-(g_cum[h * S_LEN + i0 + t] + mm));
    }

    // Load Q tile transposed with swizzle: logical Qt[d][r] at phys r^(((d>>2)&7)<<2)
    {
        const float* qp = q + (size_t)i0 * E_DIM + h * DHEAD;
#pragma unroll
        for (int iter = 0; iter < 8; iter++) {
            int idx = iter * 256 + t;       // 2048 float4s
            int row = idx >> 5;             // q-row 0..63
            int c4  = (idx & 31) * 4;       // d base
            float4 qv = *(const float4*)(qp + (size_t)row * E_DIM + c4);
            float vv[4] = {qv.x, qv.y, qv.z, qv.w};
#pragma unroll
            for (int qq = 0; qq < 4; qq++) {
                int d = c4 + qq;
                int swz = ((d >> 2) & 7) << 2;
                Qt[d * PQ + (row ^ swz)] = vv[qq];
            }
        }
    }

    float o[4][8];
#pragma unroll
    for (int i = 0; i < 4; i++)
#pragma unroll
        for (int c = 0; c < 8; c++) o[i][c] = 0.f;
    float rs[4];
#pragma unroll
    for (int i = 0; i < 4; i++) rs[i] = 0.f;

    int swzP = (ty >> 1) << 2;   // == ((ty*4+i)>>3)<<2 for i in 0..3

    for (int j0 = 0; j0 <= i0; j0 += 64) {
        __syncthreads();   // previous iter done with Kt/Vs/Ps
        {
            const float* kp = k + (size_t)j0 * E_DIM + h * DHEAD;
            const float* vp = v + (size_t)j0 * E_DIM + h * DHEAD;
#pragma unroll
            for (int iter = 0; iter < 8; iter++) {
                int idx = iter * 256 + t;
                int row = idx >> 5;
                int c4  = (idx & 31) * 4;
                float4 kv = *(const float4*)(kp + (size_t)row * E_DIM + c4);
                float4 vv = *(const float4*)(vp + (size_t)row * E_DIM + c4);
                float ka[4] = {kv.x, kv.y, kv.z, kv.w};
#pragma unroll
                for (int qq = 0; qq < 4; qq++) {
                    int d = c4 + qq;
                    int swz = ((d >> 2) & 7) << 2;
                    Kt[d * PQ + (row ^ swz)] = ka[qq];
                }
                *(float4*)(Vs + row * PV + c4) = vv;
            }
            if (t < 64) gsh[t] = g_g[h * S_LEN + j0 + t];
        }
        __syncthreads();

        // ---- S = Q K^T (64x64), 4x4 per thread ----
        float acc[4][4];
#pragma unroll
        for (int i = 0; i < 4; i++)
#pragma unroll
            for (int j = 0; j < 4; j++) acc[i][j] = 0.f;

#pragma unroll 4
        for (int kk = 0; kk < DHEAD; kk++) {
            int swz = ((kk >> 2) & 7) << 2;
            const float* qrow = Qt + kk * PQ;
            const float* krow = Kt + kk * PQ;
            float4 av = *(const float4*)(qrow + ((ty * 4) ^ swz));
            float4 bv = *(const float4*)(krow + ((tx * 4) ^ swz));
            float a[4]  = {av.x, av.y, av.z, av.w};
            float bb[4] = {bv.x, bv.y, bv.z, bv.w};
#pragma unroll
            for (int i = 0; i < 4; i++)
#pragma unroll
                for (int j = 0; j < 4; j++)
                    acc[i][j] += a[i] * bb[j];
        }

        // ---- P = S * scale * exp(g_j - M_i), causal mask, row sums ----
        bool diag = (j0 == i0);
#pragma unroll
        for (int i = 0; i < 4; i++) {
            int r = ty * 4 + i;
            float m = marr[r];
            float pv[4];
#pragma unroll
            for (int j = 0; j < 4; j++) {
                int c = tx * 4 + j;
                float val = acc[i][j] * SCALE * __expf(gsh[c] - m);
                if (diag && c > r) val = 0.f;
                rs[i] += val;
                pv[j] = val;
            }
            *(float4*)(Ps + r * PP + ((tx * 4) ^ swzP)) =
                make_float4(pv[0], pv[1], pv[2], pv[3]);
        }
        __syncthreads();

        // ---- O += P V (64x128), 4x8 per thread ----
#pragma unroll 2
        for (int j = 0; j < 64; j++) {
            float a[4];
#pragma unroll
            for (int i = 0; i < 4; i++)
                a[i] = Ps[(ty * 4 + i) * PP + (j ^ swzP)];
            float4 b0 = *(const float4*)(Vs + j * PV + tx * 8);
            float4 b1 = *(const float4*)(Vs + j * PV + tx * 8 + 4);
            float bb[8] = {b0.x, b0.y, b0.z, b0.w, b1.x, b1.y, b1.z, b1.w};
#pragma unroll
            for (int i = 0; i < 4; i++)
#pragma unroll
                for (int c = 0; c < 8; c++)
                    o[i][c] += a[i] * bb[c];
        }
    }

    // ---- epilogue: normalizer, then fused per-head LayerNorm ----
    __syncthreads();
#pragma unroll
    for (int i = 0; i < 4; i++) red1[ty * 4 + i][tx] = rs[i];
    __syncthreads();

    float sA[4], sB[4];
#pragma unroll
    for (int i = 0; i < 4; i++) {
        int r = ty * 4 + i;
        float rsum = 0.f;
#pragma unroll
        for (int x = 0; x < 16; x++) rsum += red1[r][x];
        float norm = fmaxf(fabsf(rsum), nbarr[r]) + EPS;
        float inv = 1.0f / norm;
        float a1 = 0.f, a2 = 0.f;
#pragma unroll
        for (int c = 0; c < 8; c++) {
            float val = o[i][c] * inv;
            o[i][c] = val;
            a1 += val; a2 += val * val;
        }
        sA[i] = a1; sB[i] = a2;
    }
    __syncthreads();
#pragma unroll
    for (int i = 0; i < 4; i++) { red1[ty * 4 + i][tx] = sA[i]; red2[ty * 4 + i][tx] = sB[i]; }
    __syncthreads();

#pragma unroll
    for (int i = 0; i < 4; i++) {
        int r = ty * 4 + i;
        float m1 = 0.f, m2 = 0.f;
#pragma unroll
        for (int x = 0; x < 16; x++) { m1 += red1[r][x]; m2 += red2[r][x]; }
        float mu   = m1 * (1.0f / DHEAD);
        float var  = m2 * (1.0f / DHEAD) - mu * mu;
        float rstd = rsqrtf(var + EPS);
        float res[8];
#pragma unroll
        for (int c = 0; c < 8; c++) {
            int d = tx * 8 + c;
            res[c] = (o[i][c] - mu) * rstd * lnsc[h * DHEAD + d];
        }
        float4* op = (float4*)(out + (size_t)(i0 + r) * E_DIM + h * DHEAD + tx * 8);
        op[0] = make_float4(res[0], res[1], res[2], res[3]);
        op[1] = make_float4(res[4], res[5], res[6], res[7]);
    }
}

// ---------------- launch --------------------------------------------------------
extern "C" void kernel_launch(void* const* d_in, const int* in_sizes, int n_in,
                              void* d_out, int out_size)
{
    const float* q    = (const float*)d_in[0];
    const float* k    = (const float*)d_in[1];
    const float* v    = (const float*)d_in[2];
    const float* Wi   = (const float*)d_in[3];
    const float* bi   = (const float*)d_in[4];
    const float* Wf   = (const float*)d_in[5];
    const float* bf   = (const float*)d_in[6];
    const float* lnsc = (const float*)d_in[7];
    float* out = (float*)d_out;

    cudaFuncSetAttribute(mlstm_main_kernel,
                         cudaFuncAttributeMaxDynamicSharedMemorySize, SMEM_BYTES);

    dim3 ggrid(128, 3);
    gates_kernel<<<ggrid, 128>>>(q, k, v, Wi, Wf);
    scan_kernel<<<NHEAD, 256>>>(bi, bf);
    dim3 grid(32, NHEAD);
    mlstm_main_kernel<<<grid, 256, SMEM_BYTES>>>(q, k, v, lnsc, out);
}

// round 5
// speedup vs baseline: 2.8685x; 2.8458x over previous
#include <cuda_runtime.h>
#include <cuda_bf16.h>
#include <math.h>
#include <stdint.h>

#define S_LEN 2048
#define E_DIM 1024
#define NHEAD 8
#define DHEAD 128
#define EPS 1e-6f
#define SCALE 0.08838834764831845f  /* 1/sqrt(128) */

#define DPAD 136   /* bf16 elems per row of Q/K/V planes: 128 + 8 (272B stride) */
#define PPAD 72    /* bf16 elems per row of P planes: 64 + 8 (144B stride) */

/* plane sizes in bf16 elements */
#define QKV_PLANE (64 * DPAD)      /* 8704  */
#define P_PLANE   (64 * PPAD)      /* 4608  */
#define PLANE_B   (QKV_PLANE * 2)  /* 17408 bytes per Q/K/V plane */
#define PPLANE_B  (P_PLANE * 2)    /* 9216 bytes per P plane */

/* smem layout (bf16 elems): QH QL KH KL VH VL PH PL */
#define OFF_QH 0
#define OFF_QL (OFF_QH + QKV_PLANE)
#define OFF_KH (OFF_QL + QKV_PLANE)
#define OFF_KL (OFF_KH + QKV_PLANE)
#define OFF_VH (OFF_KL + QKV_PLANE)
#define OFF_VL (OFF_VH + QKV_PLANE)
#define OFF_PH (OFF_VL + QKV_PLANE)
#define OFF_PL (OFF_PH + P_PLANE)
#define SMEM_ELEMS (OFF_PL + P_PLANE)
#define SMEM_BYTES (SMEM_ELEMS * 2)

// ---------------- scratch (device globals; no allocation allowed) --------------
__device__ float g_parti[3][NHEAD * S_LEN];
__device__ float g_partf[3][NHEAD * S_LEN];
__device__ float g_cum [NHEAD * S_LEN];
__device__ float g_g   [NHEAD * S_LEN];
__device__ float g_M   [NHEAD * S_LEN];

__device__ __forceinline__ float logsigf(float x) {
    return fminf(x, 0.0f) - log1pf(expf(-fabsf(x)));
}

// ---------------- mma / ldmatrix wrappers ---------------------------------------
__device__ __forceinline__ uint32_t s2u(const void* p) {
    return (uint32_t)__cvta_generic_to_shared(p);
}
__device__ __forceinline__ void ldsm4(uint32_t a, uint32_t r[4]) {
    asm volatile("ldmatrix.sync.aligned.m8n8.x4.shared.b16 {%0,%1,%2,%3}, [%4];"
                 : "=r"(r[0]), "=r"(r[1]), "=r"(r[2]), "=r"(r[3]) : "r"(a));
}
__device__ __forceinline__ void ldsm2(uint32_t a, uint32_t r[2]) {
    asm volatile("ldmatrix.sync.aligned.m8n8.x2.shared.b16 {%0,%1}, [%2];"
                 : "=r"(r[0]), "=r"(r[1]) : "r"(a));
}
__device__ __forceinline__ void ldsm2t(uint32_t a, uint32_t r[2]) {
    asm volatile("ldmatrix.sync.aligned.m8n8.x2.trans.shared.b16 {%0,%1}, [%2];"
                 : "=r"(r[0]), "=r"(r[1]) : "r"(a));
}
__device__ __forceinline__ void mma16816(float c[4], const uint32_t a[4], const uint32_t b[2]) {
    asm volatile(
        "mma.sync.aligned.m16n8k16.row.col.f32.bf16.bf16.f32 "
        "{%0,%1,%2,%3}, {%4,%5,%6,%7}, {%8,%9}, {%0,%1,%2,%3};"
        : "+f"(c[0]), "+f"(c[1]), "+f"(c[2]), "+f"(c[3])
        : "r"(a[0]), "r"(a[1]), "r"(a[2]), "r"(a[3]), "r"(b[0]), "r"(b[1]));
}
__device__ __forceinline__ uint32_t pack_bf2(float x, float y) {
    __nv_bfloat162 p;
    p.x = __float2bfloat16(x);
    p.y = __float2bfloat16(y);
    return *(uint32_t*)&p;
}

// ---------------- kernel 1: gate preactivations (partial sums) ------------------
__global__ __launch_bounds__(128)
void gates_kernel(const float* __restrict__ q, const float* __restrict__ k,
                  const float* __restrict__ v,
                  const float* __restrict__ Wi, const float* __restrict__ Wf)
{
    int warp = threadIdx.x >> 5, lane = threadIdx.x & 31;
    int chunk = blockIdx.y;
    int s0 = blockIdx.x * 16 + warp * 4;

    const float* src = (chunk == 0) ? q : ((chunk == 1) ? k : v);
    const float* W0 = Wi + (size_t)chunk * 1024 * 8;
    const float* W1 = Wf + (size_t)chunk * 1024 * 8;

    float acc[4][16];
#pragma unroll
    for (int r = 0; r < 4; r++)
#pragma unroll
        for (int g = 0; g < 16; g++) acc[r][g] = 0.f;

#pragma unroll 2
    for (int it = 0; it < 8; it++) {
        int e = it * 128 + lane * 4;
        float xv[4][4];
#pragma unroll
        for (int r = 0; r < 4; r++) {
            float4 xq = *(const float4*)(src + (size_t)(s0 + r) * E_DIM + e);
            xv[r][0] = xq.x; xv[r][1] = xq.y; xv[r][2] = xq.z; xv[r][3] = xq.w;
        }
#pragma unroll
        for (int s = 0; s < 4; s++) {
            float4 wi0 = *(const float4*)(W0 + (size_t)(e + s) * 8);
            float4 wi1 = *(const float4*)(W0 + (size_t)(e + s) * 8 + 4);
            float4 wf0 = *(const float4*)(W1 + (size_t)(e + s) * 8);
            float4 wf1 = *(const float4*)(W1 + (size_t)(e + s) * 8 + 4);
            float w[16] = {wi0.x, wi0.y, wi0.z, wi0.w, wi1.x, wi1.y, wi1.z, wi1.w,
                           wf0.x, wf0.y, wf0.z, wf0.w, wf1.x, wf1.y, wf1.z, wf1.w};
#pragma unroll
            for (int r = 0; r < 4; r++)
#pragma unroll
                for (int g = 0; g < 16; g++)
                    acc[r][g] += xv[r][s] * w[g];
        }
    }

#pragma unroll
    for (int r = 0; r < 4; r++)
#pragma unroll
        for (int g = 0; g < 16; g++) {
#pragma unroll
            for (int o = 16; o > 0; o >>= 1)
                acc[r][g] += __shfl_xor_sync(0xffffffffu, acc[r][g], o);
        }

#pragma unroll
    for (int g = 0; g < 16; g++) {
        if (lane == g) {
#pragma unroll
            for (int r = 0; r < 4; r++) {
                int s = s0 + r;
                if (g < 8) g_parti[chunk][g * S_LEN + s]       = acc[r][g];
                else       g_partf[chunk][(g - 8) * S_LEN + s] = acc[r][g];
            }
        }
    }
}

// ---------------- kernel 2: finalize gates + per-head scans ---------------------
__global__ void scan_kernel(const float* __restrict__ bi, const float* __restrict__ bf)
{
    int h = blockIdx.x;
    int t = threadIdx.x;
    __shared__ float sh[256];
    const int SEQ = S_LEN / 256;

    float vals[8], iv[8];
    float loc = 0.f;
    float bih = bi[h], bfh = bf[h];
#pragma unroll
    for (int j = 0; j < SEQ; j++) {
        int idx = h * S_LEN + t * SEQ + j;
        float fpre = g_partf[0][idx] + g_partf[1][idx] + g_partf[2][idx] + bfh;
        iv[j] = g_parti[0][idx] + g_parti[1][idx] + g_parti[2][idx] + bih;
        vals[j] = logsigf(fpre);
        loc += vals[j];
    }
    sh[t] = loc; __syncthreads();
    for (int off = 1; off < 256; off <<= 1) {
        float x = sh[t];
        float y = (t >= off) ? sh[t - off] : 0.f;
        __syncthreads();
        sh[t] = x + y;
        __syncthreads();
    }
    float c = (t > 0) ? sh[t - 1] : 0.f;

    float gv[8];
    float lm = -INFINITY;
#pragma unroll
    for (int j = 0; j < SEQ; j++) {
        c += vals[j];
        g_cum[h * S_LEN + t * SEQ + j] = c;
        float gg = iv[j] - c;
        gv[j] = gg;
        g_g[h * S_LEN + t * SEQ + j] = gg;
        lm = fmaxf(lm, gg);
    }
    __syncthreads();
    sh[t] = lm; __syncthreads();
    for (int off = 1; off < 256; off <<= 1) {
        float x = sh[t];
        float y = (t >= off) ? sh[t - off] : -INFINITY;
        __syncthreads();
        sh[t] = fmaxf(x, y);
        __syncthreads();
    }
    float m = (t > 0) ? sh[t - 1] : -INFINITY;
#pragma unroll
    for (int j = 0; j < SEQ; j++) {
        m = fmaxf(m, gv[j]);
        g_M[h * S_LEN + t * SEQ + j] = m;
    }
}

// ---------------- kernel 3: tensor-core mLSTM attention + normalize + LN --------
// Block = (head, 64-row q tile), 256 threads = 8 warps.
// 3xBF16 split mma: S = Qh.Kh + Qh.Kl + Ql.Kh ; O = Ph.Vh + Ph.Vl + Pl.Vh.
__global__ __launch_bounds__(256, 1)
void mlstm_main_kernel(const float* __restrict__ q, const float* __restrict__ k,
                       const float* __restrict__ v, const float* __restrict__ lnsc,
                       float* __restrict__ out)
{
    extern __shared__ __nv_bfloat16 sm[];
    __nv_bfloat16* QH = sm + OFF_QH;
    __nv_bfloat16* KH = sm + OFF_KH;
    __nv_bfloat16* VH = sm + OFF_VH;
    __nv_bfloat16* PH = sm + OFF_PH;
    __shared__ float marr[64], nbarr[64], gsh[64];
    __shared__ float redr[64][2], red1[64][2], red2[64][2];

    int t    = threadIdx.x;
    int lane = t & 31;
    int w    = t >> 5;
    int mw   = w & 3;          // m-block: rows mw*16 .. +16
    int nh   = w >> 2;         // n-half
    int h    = blockIdx.y;
    int it   = (gridDim.x - 1) - blockIdx.x;
    int i0   = it * 64;

    int lq = lane >> 2;        // 0..7
    int l4 = lane & 3;         // 0..3
    int m0 = mw * 16;
    int r0l = m0 + lq, r1l = r0l + 8;

    if (t < 64) {
        float mm = g_M[h * S_LEN + i0 + t];
        marr[t]  = mm;
        nbarr[t] = __expf(-(g_cum[h * S_LEN + i0 + t] + mm));
    }

    // ---- build Q hi/lo planes (once) ----
    {
        const float* qp = q + (size_t)i0 * E_DIM + h * DHEAD;
#pragma unroll
        for (int iter = 0; iter < 8; iter++) {
            int idx = iter * 256 + t;
            int row = idx >> 5;
            int d4  = (idx & 31) * 4;
            float4 x = *(const float4*)(qp + (size_t)row * E_DIM + d4);
            float xs[4] = {x.x, x.y, x.z, x.w};
            __nv_bfloat16 hh[4]; float lo[4];
#pragma unroll
            for (int jj = 0; jj < 4; jj++) {
                hh[jj] = __float2bfloat16(xs[jj]);
                lo[jj] = xs[jj] - __bfloat162float(hh[jj]);
            }
            uint2 uh, ul;
            { __nv_bfloat162 p; p.x = hh[0]; p.y = hh[1]; uh.x = *(uint32_t*)&p;
              p.x = hh[2]; p.y = hh[3]; uh.y = *(uint32_t*)&p; }
            ul.x = pack_bf2(lo[0], lo[1]);
            ul.y = pack_bf2(lo[2], lo[3]);
            int off = row * DPAD + d4;
            *(uint2*)(QH + off)             = uh;
            *(uint2*)(QH + QKV_PLANE + off) = ul;
        }
    }

    float oacc[8][4];
#pragma unroll
    for (int nf = 0; nf < 8; nf++)
#pragma unroll
        for (int c = 0; c < 4; c++) oacc[nf][c] = 0.f;
    float rs0 = 0.f, rs1 = 0.f;

    for (int j0 = 0; j0 <= i0; j0 += 64) {
        __syncthreads();   // prev O-phase done with V/P; Q planes ready (first iter)

        // ---- load+split K and V tiles ----
        {
            const float* kp = k + (size_t)j0 * E_DIM + h * DHEAD;
            const float* vp = v + (size_t)j0 * E_DIM + h * DHEAD;
#pragma unroll
            for (int iter = 0; iter < 8; iter++) {
                int idx = iter * 256 + t;
                int row = idx >> 5;
                int d4  = (idx & 31) * 4;
                int off = row * DPAD + d4;
                float4 xk = *(const float4*)(kp + (size_t)row * E_DIM + d4);
                float4 xv = *(const float4*)(vp + (size_t)row * E_DIM + d4);
                float ks4[4] = {xk.x, xk.y, xk.z, xk.w};
                float vs4[4] = {xv.x, xv.y, xv.z, xv.w};
                __nv_bfloat16 bh;
                float lo;
                uint2 uh, ul;
                // K
                bh = __float2bfloat16(ks4[0]); lo = ks4[0] - __bfloat162float(bh);
                float l0 = lo; __nv_bfloat16 h0 = bh;
                bh = __float2bfloat16(ks4[1]); lo = ks4[1] - __bfloat162float(bh);
                { __nv_bfloat162 p; p.x = h0; p.y = bh; uh.x = *(uint32_t*)&p; }
                ul.x = pack_bf2(l0, lo);
                bh = __float2bfloat16(ks4[2]); lo = ks4[2] - __bfloat162float(bh);
                l0 = lo; h0 = bh;
                bh = __float2bfloat16(ks4[3]); lo = ks4[3] - __bfloat162float(bh);
                { __nv_bfloat162 p; p.x = h0; p.y = bh; uh.y = *(uint32_t*)&p; }
                ul.y = pack_bf2(l0, lo);
                *(uint2*)(KH + off)             = uh;
                *(uint2*)(KH + QKV_PLANE + off) = ul;
                // V
                bh = __float2bfloat16(vs4[0]); lo = vs4[0] - __bfloat162float(bh);
                l0 = lo; h0 = bh;
                bh = __float2bfloat16(vs4[1]); lo = vs4[1] - __bfloat162float(bh);
                { __nv_bfloat162 p; p.x = h0; p.y = bh; uh.x = *(uint32_t*)&p; }
                ul.x = pack_bf2(l0, lo);
                bh = __float2bfloat16(vs4[2]); lo = vs4[2] - __bfloat162float(bh);
                l0 = lo; h0 = bh;
                bh = __float2bfloat16(vs4[3]); lo = vs4[3] - __bfloat162float(bh);
                { __nv_bfloat162 p; p.x = h0; p.y = bh; uh.y = *(uint32_t*)&p; }
                ul.y = pack_bf2(l0, lo);
                *(uint2*)(VH + off)             = uh;
                *(uint2*)(VH + QKV_PLANE + off) = ul;
            }
            if (t < 64) gsh[t] = g_g[h * S_LEN + j0 + t];
        }
        __syncthreads();

        // ---- S = Q K^T (64x64) via 3xBF16 mma; warp tile 16x32 ----
        float sacc[4][4];
#pragma unroll
        for (int nf = 0; nf < 4; nf++)
#pragma unroll
            for (int c = 0; c < 4; c++) sacc[nf][c] = 0.f;

#pragma unroll
        for (int ks = 0; ks < 8; ks++) {
            int k0 = ks * 16;
            uint32_t aH[4], aL[4], bH[2], bL[2];
            uint32_t aaddr = s2u(QH + (m0 + (lane & 15)) * DPAD + k0 + (lane >> 4) * 8);
            ldsm4(aaddr, aH);
            ldsm4(aaddr + PLANE_B, aL);
#pragma unroll
            for (int nf = 0; nf < 4; nf++) {
                int n0 = nh * 32 + nf * 8;
                uint32_t baddr = s2u(KH + (n0 + (lane & 7)) * DPAD + k0 + ((lane >> 3) & 1) * 8);
                ldsm2(baddr, bH);
                ldsm2(baddr + PLANE_B, bL);
                mma16816(sacc[nf], aH, bH);
                mma16816(sacc[nf], aH, bL);
                mma16816(sacc[nf], aL, bH);
            }
        }

        // ---- P = S*scale*exp(g_c - M_r), causal mask, row sums, split to bf16 ----
        bool diag = (j0 == i0);
        float mi0 = marr[r0l], mi1 = marr[r1l];
#pragma unroll
        for (int nf = 0; nf < 4; nf++) {
            int c0 = nh * 32 + nf * 8 + 2 * l4;
            float e0 = __expf(gsh[c0]     - mi0) * SCALE;
            float e1 = __expf(gsh[c0 + 1] - mi0) * SCALE;
            float e2 = __expf(gsh[c0]     - mi1) * SCALE;
            float e3 = __expf(gsh[c0 + 1] - mi1) * SCALE;
            float v00 = sacc[nf][0] * e0;
            float v01 = sacc[nf][1] * e1;
            float v10 = sacc[nf][2] * e2;
            float v11 = sacc[nf][3] * e3;
            if (diag) {
                if (c0     > r0l) v00 = 0.f;
                if (c0 + 1 > r0l) v01 = 0.f;
                if (c0     > r1l) v10 = 0.f;
                if (c0 + 1 > r1l) v11 = 0.f;
            }
            rs0 += v00 + v01;
            rs1 += v10 + v11;
            __nv_bfloat16 h00 = __float2bfloat16(v00), h01 = __float2bfloat16(v01);
            __nv_bfloat16 h10 = __float2bfloat16(v10), h11 = __float2bfloat16(v11);
            uint32_t ph0, ph1;
            { __nv_bfloat162 p; p.x = h00; p.y = h01; ph0 = *(uint32_t*)&p;
              p.x = h10; p.y = h11; ph1 = *(uint32_t*)&p; }
            uint32_t pl0 = pack_bf2(v00 - __bfloat162float(h00), v01 - __bfloat162float(h01));
            uint32_t pl1 = pack_bf2(v10 - __bfloat162float(h10), v11 - __bfloat162float(h11));
            *(uint32_t*)(PH + r0l * PPAD + c0)           = ph0;
            *(uint32_t*)(PH + r1l * PPAD + c0)           = ph1;
            *(uint32_t*)(PH + P_PLANE + r0l * PPAD + c0) = pl0;
            *(uint32_t*)(PH + P_PLANE + r1l * PPAD + c0) = pl1;
        }
        __syncthreads();

        // ---- O += P V (64x128) via 3xBF16 mma; warp tile 16x64 ----
#pragma unroll
        for (int ks = 0; ks < 4; ks++) {
            int k0 = ks * 16;
            uint32_t aH[4], aL[4], bH[2], bL[2];
            uint32_t aaddr = s2u(PH + (m0 + (lane & 15)) * PPAD + k0 + (lane >> 4) * 8);
            ldsm4(aaddr, aH);
            ldsm4(aaddr + PPLANE_B, aL);
#pragma unroll
            for (int nf = 0; nf < 8; nf++) {
                int n0 = nh * 64 + nf * 8;
                uint32_t baddr = s2u(VH + (k0 + (lane & 7) + ((lane >> 3) & 1) * 8) * DPAD + n0);
                ldsm2t(baddr, bH);
                ldsm2t(baddr + PLANE_B, bL);
                mma16816(oacc[nf], aH, bH);
                mma16816(oacc[nf], aH, bL);
                mma16816(oacc[nf], aL, bH);
            }
        }
    }

    // ---- epilogue: normalizer + fused LayerNorm ----
    rs0 += __shfl_xor_sync(0xffffffffu, rs0, 1);
    rs0 += __shfl_xor_sync(0xffffffffu, rs0, 2);
    rs1 += __shfl_xor_sync(0xffffffffu, rs1, 1);
    rs1 += __shfl_xor_sync(0xffffffffu, rs1, 2);
    if (l4 == 0) { redr[r0l][nh] = rs0; redr[r1l][nh] = rs1; }
    __syncthreads();

    float inv0 = 1.0f / (fmaxf(fabsf(redr[r0l][0] + redr[r0l][1]), nbarr[r0l]) + EPS);
    float inv1 = 1.0f / (fmaxf(fabsf(redr[r1l][0] + redr[r1l][1]), nbarr[r1l]) + EPS);

    float a10 = 0.f, a20 = 0.f, a11 = 0.f, a21 = 0.f;
#pragma unroll
    for (int nf = 0; nf < 8; nf++) {
        oacc[nf][0] *= inv0; oacc[nf][1] *= inv0;
        oacc[nf][2] *= inv1; oacc[nf][3] *= inv1;
        a10 += oacc[nf][0] + oacc[nf][1];
        a20 += oacc[nf][0] * oacc[nf][0] + oacc[nf][1] * oacc[nf][1];
        a11 += oacc[nf][2] + oacc[nf][3];
        a21 += oacc[nf][2] * oacc[nf][2] + oacc[nf][3] * oacc[nf][3];
    }
    a10 += __shfl_xor_sync(0xffffffffu, a10, 1);
    a10 += __shfl_xor_sync(0xffffffffu, a10, 2);
    a20 += __shfl_xor_sync(0xffffffffu, a20, 1);
    a20 += __shfl_xor_sync(0xffffffffu, a20, 2);
    a11 += __shfl_xor_sync(0xffffffffu, a11, 1);
    a11 += __shfl_xor_sync(0xffffffffu, a11, 2);
    a21 += __shfl_xor_sync(0xffffffffu, a21, 1);
    a21 += __shfl_xor_sync(0xffffffffu, a21, 2);
    if (l4 == 0) {
        red1[r0l][nh] = a10; red2[r0l][nh] = a20;
        red1[r1l][nh] = a11; red2[r1l][nh] = a21;
    }
    __syncthreads();

    float mu0  = (red1[r0l][0] + red1[r0l][1]) * (1.0f / DHEAD);
    float var0 = (red2[r0l][0] + red2[r0l][1]) * (1.0f / DHEAD) - mu0 * mu0;
    float rstd0 = rsqrtf(var0 + EPS);
    float mu1  = (red1[r1l][0] + red1[r1l][1]) * (1.0f / DHEAD);
    float var1 = (red2[r1l][0] + red2[r1l][1]) * (1.0f / DHEAD) - mu1 * mu1;
    float rstd1 = rsqrtf(var1 + EPS);

#pragma unroll
    for (int nf = 0; nf < 8; nf++) {
        int col = nh * 64 + nf * 8 + 2 * l4;
        float w0 = lnsc[h * DHEAD + col];
        float w1 = lnsc[h * DHEAD + col + 1];
        float2 o0, o1;
        o0.x = (oacc[nf][0] - mu0) * rstd0 * w0;
        o0.y = (oacc[nf][1] - mu0) * rstd0 * w1;
        o1.x = (oacc[nf][2] - mu1) * rstd1 * w0;
        o1.y = (oacc[nf][3] - mu1) * rstd1 * w1;
        *(float2*)(out + (size_t)(i0 + r0l) * E_DIM + h * DHEAD + col) = o0;
        *(float2*)(out + (size_t)(i0 + r1l) * E_DIM + h * DHEAD + col) = o1;
    }
}

// ---------------- launch --------------------------------------------------------
extern "C" void kernel_launch(void* const* d_in, const int* in_sizes, int n_in,
                              void* d_out, int out_size)
{
    const float* q    = (const float*)d_in[0];
    const float* k    = (const float*)d_in[1];
    const float* v    = (const float*)d_in[2];
    const float* Wi   = (const float*)d_in[3];
    const float* bi   = (const float*)d_in[4];
    const float* Wf   = (const float*)d_in[5];
    const float* bf   = (const float*)d_in[6];
    const float* lnsc = (const float*)d_in[7];
    float* out = (float*)d_out;

    cudaFuncSetAttribute(mlstm_main_kernel,
                         cudaFuncAttributeMaxDynamicSharedMemorySize, SMEM_BYTES);

    dim3 ggrid(128, 3);
    gates_kernel<<<ggrid, 128>>>(q, k, v, Wi, Wf);
    scan_kernel<<<NHEAD, 256>>>(bi, bf);
    dim3 grid(32, NHEAD);
    mlstm_main_kernel<<<grid, 256, SMEM_BYTES>>>(q, k, v, lnsc, out);
}

// round 7
// speedup vs baseline: 3.0263x; 1.0550x over previous
#include <cuda_runtime.h>
#include <cuda_bf16.h>
#include <math.h>
#include <stdint.h>

#define S_LEN 2048
#define E_DIM 1024
#define NHEAD 8
#define DHEAD 128
#define EPS 1e-6f
#define SCALE 0.08838834764831845f  /* 1/sqrt(128) */

#define DPAD 136   /* bf16 elems per row of Q/K/V smem planes: 128 + 8 */
#define PPAD 72    /* bf16 elems per row of P smem planes: 64 + 8 */

#define QKV_PLANE (64 * DPAD)
#define P_PLANE   (64 * PPAD)
#define PLANE_B   (QKV_PLANE * 2)
#define PPLANE_B  (P_PLANE * 2)

#define OFF_QH 0
#define OFF_QL (OFF_QH + QKV_PLANE)
#define OFF_KH (OFF_QL + QKV_PLANE)
#define OFF_KL (OFF_KH + QKV_PLANE)
#define OFF_VH (OFF_KL + QKV_PLANE)
#define OFF_VL (OFF_VH + QKV_PLANE)
#define OFF_PH (OFF_VL + QKV_PLANE)
#define OFF_PL (OFF_PH + P_PLANE)
#define SMEM_ELEMS (OFF_PL + P_PLANE)
#define SMEM_BYTES (SMEM_ELEMS * 2)

// ---------------- scratch (device globals; no allocation allowed) --------------
__device__ float g_parti[3][NHEAD * S_LEN];
__device__ float g_partf[3][NHEAD * S_LEN];
__device__ float g_cum [NHEAD * S_LEN];
__device__ float g_g   [NHEAD * S_LEN];
__device__ float g_M   [NHEAD * S_LEN];
// pre-split bf16 planes: [tensor q/k/v][hi/lo][head][s][d]
__device__ __nv_bfloat16 g_plane[3][2][NHEAD][S_LEN][DHEAD];

__device__ __forceinline__ float logsigf(float x) {
    return fminf(x, 0.0f) - log1pf(expf(-fabsf(x)));
}

// ---------------- mma / ldmatrix wrappers ---------------------------------------
__device__ __forceinline__ uint32_t s2u(const void* p) {
    return (uint32_t)__cvta_generic_to_shared(p);
}
__device__ __forceinline__ void ldsm4(uint32_t a, uint32_t r[4]) {
    asm volatile("ldmatrix.sync.aligned.m8n8.x4.shared.b16 {%0,%1,%2,%3}, [%4];"
                 : "=r"(r[0]), "=r"(r[1]), "=r"(r[2]), "=r"(r[3]) : "r"(a));
}
__device__ __forceinline__ void ldsm4t(uint32_t a, uint32_t r[4]) {
    asm volatile("ldmatrix.sync.aligned.m8n8.x4.trans.shared.b16 {%0,%1,%2,%3}, [%4];"
                 : "=r"(r[0]), "=r"(r[1]), "=r"(r[2]), "=r"(r[3]) : "r"(a));
}
__device__ __forceinline__ void mma16816(float c[4], const uint32_t a[4], const uint32_t b[2]) {
    asm volatile(
        "mma.sync.aligned.m16n8k16.row.col.f32.bf16.bf16.f32 "
        "{%0,%1,%2,%3}, {%4,%5,%6,%7}, {%8,%9}, {%0,%1,%2,%3};"
        : "+f"(c[0]), "+f"(c[1]), "+f"(c[2]), "+f"(c[3])
        : "r"(a[0]), "r"(a[1]), "r"(a[2]), "r"(a[3]), "r"(b[0]), "r"(b[1]));
}
__device__ __forceinline__ uint32_t pack_bf2(float x, float y) {
    __nv_bfloat162 p;
    p.x = __float2bfloat16(x);
    p.y = __float2bfloat16(y);
    return *(uint32_t*)&p;
}

// ---------------- kernel 0: split q/k/v into bf16 hi/lo planes ------------------
// grid (2048, 3), 256 threads; each thread converts 4 floats.
__global__ __launch_bounds__(256)
void preconvert_kernel(const float* __restrict__ q, const float* __restrict__ k,
                       const float* __restrict__ v)
{
    int tensor = blockIdx.y;
    const float* src = (tensor == 0) ? q : ((tensor == 1) ? k : v);
    int fi = (blockIdx.x * 256 + threadIdx.x) * 4;   // s*1024 + e
    int s = fi >> 10;
    int e = fi & 1023;
    int h = e >> 7, d = e & 127;

    float4 x = *(const float4*)(src + fi);
    float xs[4] = {x.x, x.y, x.z, x.w};
    __nv_bfloat16 hh[4]; float lo[4];
#pragma unroll
    for (int j = 0; j < 4; j++) {
        hh[j] = __float2bfloat16(xs[j]);
        lo[j] = xs[j] - __bfloat162float(hh[j]);
    }
    uint2 uh, ul;
    { __nv_bfloat162 p; p.x = hh[0]; p.y = hh[1]; uh.x = *(uint32_t*)&p;
      p.x = hh[2]; p.y = hh[3]; uh.y = *(uint32_t*)&p; }
    ul.x = pack_bf2(lo[0], lo[1]);
    ul.y = pack_bf2(lo[2], lo[3]);
    *(uint2*)&g_plane[tensor][0][h][s][d] = uh;
    *(uint2*)&g_plane[tensor][1][h][s][d] = ul;
}

// ---------------- kernel 1: gate preactivations (smem-staged weights) -----------
// grid (64, 3): x = 32-row group, y = e-chunk. 256 threads = 8 warps x 4 rows.
// Weights transposed into smem once per block; inner LDS is stride-1 broadcast-free.
__global__ __launch_bounds__(256)
void gates_kernel(const float* __restrict__ q, const float* __restrict__ k,
                  const float* __restrict__ v,
                  const float* __restrict__ Wi, const float* __restrict__ Wf)
{
    extern __shared__ float Wt[];   // [16][1024]
    int chunk = blockIdx.y;
    const float* src = (chunk == 0) ? q : ((chunk == 1) ? k : v);

    // stage weights transposed: Wt[g][e] (g 0..7 = i-gates, 8..15 = f-gates)
    for (int idx = threadIdx.x; idx < 2048; idx += 256) {
        int e = idx >> 1, half = idx & 1;
        float4 wv = *(const float4*)(Wi + (size_t)(chunk * 1024 + e) * 8 + half * 4);
        Wt[(half * 4 + 0) * 1024 + e] = wv.x;
        Wt[(half * 4 + 1) * 1024 + e] = wv.y;
        Wt[(half * 4 + 2) * 1024 + e] = wv.z;
        Wt[(half * 4 + 3) * 1024 + e] = wv.w;
        float4 wf = *(const float4*)(Wf + (size_t)(chunk * 1024 + e) * 8 + half * 4);
        Wt[(8 + half * 4 + 0) * 1024 + e] = wf.x;
        Wt[(8 + half * 4 + 1) * 1024 + e] = wf.y;
        Wt[(8 + half * 4 + 2) * 1024 + e] = wf.z;
        Wt[(8 + half * 4 + 3) * 1024 + e] = wf.w;
    }
    __syncthreads();

    int warp = threadIdx.x >> 5, lane = threadIdx.x & 31;
    int s0 = blockIdx.x * 32 + warp * 4;
    // FIX (round 6 bug): src is already the per-chunk tensor; NO chunk offset here.
    const float* sp = src + (size_t)s0 * E_DIM + lane;

    float acc[4][16];
#pragma unroll
    for (int r = 0; r < 4; r++)
#pragma unroll
        for (int g = 0; g < 16; g++) acc[r][g] = 0.f;

#pragma unroll 2
    for (int eb = 0; eb < 1024; eb += 32) {
        float xv[4];
#pragma unroll
        for (int r = 0; r < 4; r++) xv[r] = sp[(size_t)r * E_DIM + eb];
#pragma unroll
        for (int g = 0; g < 16; g++) {
            float w = Wt[g * 1024 + eb + lane];
#pragma unroll
            for (int r = 0; r < 4; r++) acc[r][g] += xv[r] * w;
        }
    }

#pragma unroll
    for (int r = 0; r < 4; r++)
#pragma unroll
        for (int g = 0; g < 16; g++) {
#pragma unroll
            for (int o = 16; o > 0; o >>= 1)
                acc[r][g] += __shfl_xor_sync(0xffffffffu, acc[r][g], o);
        }

#pragma unroll
    for (int g = 0; g < 16; g++) {
        if (lane == g) {
#pragma unroll
            for (int r = 0; r < 4; r++) {
                int s = s0 + r;
                if (g < 8) g_parti[chunk][g * S_LEN + s]       = acc[r][g];
                else       g_partf[chunk][(g - 8) * S_LEN + s] = acc[r][g];
            }
        }
    }
}

// ---------------- kernel 2: finalize gates + per-head scans ---------------------
__global__ void scan_kernel(const float* __restrict__ bi, const float* __restrict__ bf)
{
    int h = blockIdx.x;
    int t = threadIdx.x;
    __shared__ float sh[256];
    const int SEQ = S_LEN / 256;

    float vals[8], iv[8];
    float loc = 0.f;
    float bih = bi[h], bfh = bf[h];
#pragma unroll
    for (int j = 0; j < SEQ; j++) {
        int idx = h * S_LEN + t * SEQ + j;
        float fpre = g_partf[0][idx] + g_partf[1][idx] + g_partf[2][idx] + bfh;
        iv[j] = g_parti[0][idx] + g_parti[1][idx] + g_parti[2][idx] + bih;
        vals[j] = logsigf(fpre);
        loc += vals[j];
    }
    sh[t] = loc; __syncthreads();
    for (int off = 1; off < 256; off <<= 1) {
        float x = sh[t];
        float y = (t >= off) ? sh[t - off] : 0.f;
        __syncthreads();
        sh[t] = x + y;
        __syncthreads();
    }
    float c = (t > 0) ? sh[t - 1] : 0.f;

    float gv[8];
    float lm = -INFINITY;
#pragma unroll
    for (int j = 0; j < SEQ; j++) {
        c += vals[j];
        g_cum[h * S_LEN + t * SEQ + j] = c;
        float gg = iv[j] - c;
        gv[j] = gg;
        g_g[h * S_LEN + t * SEQ + j] = gg;
        lm = fmaxf(lm, gg);
    }
    __syncthreads();
    sh[t] = lm; __syncthreads();
    for (int off = 1; off < 256; off <<= 1) {
        float x = sh[t];
        float y = (t >= off) ? sh[t - off] : -INFINITY;
        __syncthreads();
        sh[t] = fmaxf(x, y);
        __syncthreads();
    }
    float m = (t > 0) ? sh[t - 1] : -INFINITY;
#pragma unroll
    for (int j = 0; j < SEQ; j++) {
        m = fmaxf(m, gv[j]);
        g_M[h * S_LEN + t * SEQ + j] = m;
    }
}

// ---------------- kernel 3: tensor-core mLSTM attention + normalize + LN --------
// Block = (head, 64-row q tile), 256 threads = 8 warps.
// Planes preconverted; loads are pure 16B copies. 3xBF16 split mma.
__global__ __launch_bounds__(256, 1)
void mlstm_main_kernel(const float* __restrict__ lnsc, float* __restrict__ out)
{
    extern __shared__ __nv_bfloat16 sm[];
    __nv_bfloat16* QH = sm + OFF_QH;
    __nv_bfloat16* KH = sm + OFF_KH;
    __nv_bfloat16* VH = sm + OFF_VH;
    __nv_bfloat16* PH = sm + OFF_PH;
    __shared__ float marr[64], nbarr[64], gsh[64];
    __shared__ float redr[64][2], red1[64][2], red2[64][2];

    int t    = threadIdx.x;
    int lane = t & 31;
    int w    = t >> 5;
    int mw   = w & 3;
    int nh   = w >> 2;
    int h    = blockIdx.y;
    int it   = (gridDim.x - 1) - blockIdx.x;
    int i0   = it * 64;

    int lq = lane >> 2;
    int l4 = lane & 3;
    int m0 = mw * 16;
    int r0l = m0 + lq, r1l = r0l + 8;

    if (t < 64) {
        float mm = g_M[h * S_LEN + i0 + t];
        marr[t]  = mm;
        nbarr[t] = __expf(-(g_cum[h * S_LEN + i0 + t] + mm));
    }

    // ---- copy Q hi/lo planes into smem ----
    {
        const __nv_bfloat16* qhp = &g_plane[0][0][h][i0][0];
        const __nv_bfloat16* qlp = &g_plane[0][1][h][i0][0];
#pragma unroll
        for (int iter = 0; iter < 4; iter++) {
            int idx = iter * 256 + t;       // 1024 x 16B per plane
            int row = idx >> 4;
            int c8  = (idx & 15) * 8;
            *(uint4*)(QH + row * DPAD + c8)             = *(const uint4*)(qhp + row * DHEAD + c8);
            *(uint4*)(QH + QKV_PLANE + row * DPAD + c8) = *(const uint4*)(qlp + row * DHEAD + c8);
        }
    }

    float oacc[8][4];
#pragma unroll
    for (int nf = 0; nf < 8; nf++)
#pragma unroll
        for (int c = 0; c < 4; c++) oacc[nf][c] = 0.f;
    float rs0 = 0.f, rs1 = 0.f;

    for (int j0 = 0; j0 <= i0; j0 += 64) {
        __syncthreads();

        // ---- copy K/V hi/lo planes (pure 16B copies) ----
        {
            const __nv_bfloat16* khp = &g_plane[1][0][h][j0][0];
            const __nv_bfloat16* klp = &g_plane[1][1][h][j0][0];
            const __nv_bfloat16* vhp = &g_plane[2][0][h][j0][0];
            const __nv_bfloat16* vlp = &g_plane[2][1][h][j0][0];
#pragma unroll
            for (int iter = 0; iter < 4; iter++) {
                int idx = iter * 256 + t;
                int row = idx >> 4;
                int c8  = (idx & 15) * 8;
                int so = row * DPAD + c8;
                int go = row * DHEAD + c8;
                *(uint4*)(KH + so)             = *(const uint4*)(khp + go);
                *(uint4*)(KH + QKV_PLANE + so) = *(const uint4*)(klp + go);
                *(uint4*)(VH + so)             = *(const uint4*)(vhp + go);
                *(uint4*)(VH + QKV_PLANE + so) = *(const uint4*)(vlp + go);
            }
            if (t < 64) gsh[t] = g_g[h * S_LEN + j0 + t];
        }
        __syncthreads();

        // ---- S = Q K^T (64x64); warp tile 16x32; x4 ldsm for A and B ----
        float sacc[4][4];
#pragma unroll
        for (int nf = 0; nf < 4; nf++)
#pragma unroll
            for (int c = 0; c < 4; c++) sacc[nf][c] = 0.f;

#pragma unroll
        for (int ks = 0; ks < 8; ks++) {
            int k0 = ks * 16;
            uint32_t aH[4], aL[4];
            uint32_t aaddr = s2u(QH + (m0 + (lane & 15)) * DPAD + k0 + (lane >> 4) * 8);
            ldsm4(aaddr, aH);
            ldsm4(aaddr + PLANE_B, aL);
#pragma unroll
            for (int g = 0; g < 2; g++) {
                int n0 = nh * 32 + g * 16;
                uint32_t bH[4], bL[4];
                uint32_t baddr = s2u(KH + (n0 + (lane & 15)) * DPAD + k0 + (lane >> 4) * 8);
                ldsm4(baddr, bH);
                ldsm4(baddr + PLANE_B, bL);
                uint32_t b0H[2] = {bH[0], bH[2]}, b1H[2] = {bH[1], bH[3]};
                uint32_t b0L[2] = {bL[0], bL[2]}, b1L[2] = {bL[1], bL[3]};
                mma16816(sacc[g * 2],     aH, b0H);
                mma16816(sacc[g * 2],     aH, b0L);
                mma16816(sacc[g * 2],     aL, b0H);
                mma16816(sacc[g * 2 + 1], aH, b1H);
                mma16816(sacc[g * 2 + 1], aH, b1L);
                mma16816(sacc[g * 2 + 1], aL, b1H);
            }
        }

        // ---- P = S*scale*exp(g_c - M_r), causal mask, row sums, split to bf16 ----
        bool diag = (j0 == i0);
        float mi0 = marr[r0l], mi1 = marr[r1l];
#pragma unroll
        for (int nf = 0; nf < 4; nf++) {
            int c0 = nh * 32 + nf * 8 + 2 * l4;
            float e0 = __expf(gsh[c0]     - mi0) * SCALE;
            float e1 = __expf(gsh[c0 + 1] - mi0) * SCALE;
            float e2 = __expf(gsh[c0]     - mi1) * SCALE;
            float e3 = __expf(gsh[c0 + 1] - mi1) * SCALE;
            float v00 = sacc[nf][0] * e0;
            float v01 = sacc[nf][1] * e1;
            float v10 = sacc[nf][2] * e2;
            float v11 = sacc[nf][3] * e3;
            if (diag) {
                if (c0     > r0l) v00 = 0.f;
                if (c0 + 1 > r0l) v01 = 0.f;
                if (c0     > r1l) v10 = 0.f;
                if (c0 + 1 > r1l) v11 = 0.f;
            }
            rs0 += v00 + v01;
            rs1 += v10 + v11;
            __nv_bfloat16 h00 = __float2bfloat16(v00), h01 = __float2bfloat16(v01);
            __nv_bfloat16 h10 = __float2bfloat16(v10), h11 = __float2bfloat16(v11);
            uint32_t ph0, ph1;
            { __nv_bfloat162 p; p.x = h00; p.y = h01; ph0 = *(uint32_t*)&p;
              p.x = h10; p.y = h11; ph1 = *(uint32_t*)&p; }
            uint32_t pl0 = pack_bf2(v00 - __bfloat162float(h00), v01 - __bfloat162float(h01));
            uint32_t pl1 = pack_bf2(v10 - __bfloat162float(h10), v11 - __bfloat162float(h11));
            *(uint32_t*)(PH + r0l * PPAD + c0)           = ph0;
            *(uint32_t*)(PH + r1l * PPAD + c0)           = ph1;
            *(uint32_t*)(PH + P_PLANE + r0l * PPAD + c0) = pl0;
            *(uint32_t*)(PH + P_PLANE + r1l * PPAD + c0) = pl1;
        }
        __syncthreads();

        // ---- O += P V (64x128); warp tile 16x64; x4.trans ldsm for V ----
#pragma unroll
        for (int ks = 0; ks < 4; ks++) {
            int k0 = ks * 16;
            uint32_t aH[4], aL[4];
            uint32_t aaddr = s2u(PH + (m0 + (lane & 15)) * PPAD + k0 + (lane >> 4) * 8);
            ldsm4(aaddr, aH);
            ldsm4(aaddr + PPLANE_B, aL);
#pragma unroll
            for (int g = 0; g < 4; g++) {
                int n0 = nh * 64 + g * 16;
                uint32_t bH[4], bL[4];
                uint32_t baddr = s2u(VH + (k0 + (lane & 7) + ((lane >> 3) & 1) * 8) * DPAD
                                        + n0 + (lane >> 4) * 8);
                ldsm4t(baddr, bH);
                ldsm4t(baddr + PLANE_B, bL);
                uint32_t b0H[2] = {bH[0], bH[1]}, b1H[2] = {bH[2], bH[3]};
                uint32_t b0L[2] = {bL[0], bL[1]}, b1L[2] = {bL[2], bL[3]};
                mma16816(oacc[g * 2],     aH, b0H);
                mma16816(oacc[g * 2],     aH, b0L);
                mma16816(oacc[g * 2],     aL, b0H);
                mma16816(oacc[g * 2 + 1], aH, b1H);
                mma16816(oacc[g * 2 + 1], aH, b1L);
                mma16816(oacc[g * 2 + 1], aL, b1H);
            }
        }
    }

    // ---- epilogue: normalizer + fused LayerNorm ----
    rs0 += __shfl_xor_sync(0xffffffffu, rs0, 1);
    rs0 += __shfl_xor_sync(0xffffffffu, rs0, 2);
    rs1 += __shfl_xor_sync(0xffffffffu, rs1, 1);
    rs1 += __shfl_xor_sync(0xffffffffu, rs1, 2);
    if (l4 == 0) { redr[r0l][nh] = rs0; redr[r1l][nh] = rs1; }
    __syncthreads();

    float inv0 = 1.0f / (fmaxf(fabsf(redr[r0l][0] + redr[r0l][1]), nbarr[r0l]) + EPS);
    float inv1 = 1.0f / (fmaxf(fabsf(redr[r1l][0] + redr[r1l][1]), nbarr[r1l]) + EPS);

    float a10 = 0.f, a20 = 0.f, a11 = 0.f, a21 = 0.f;
#pragma unroll
    for (int nf = 0; nf < 8; nf++) {
        oacc[nf][0] *= inv0; oacc[nf][1] *= inv0;
        oacc[nf][2] *= inv1; oacc[nf][3] *= inv1;
        a10 += oacc[nf][0] + oacc[nf][1];
        a20 += oacc[nf][0] * oacc[nf][0] + oacc[nf][1] * oacc[nf][1];
        a11 += oacc[nf][2] + oacc[nf][3];
        a21 += oacc[nf][2] * oacc[nf][2] + oacc[nf][3] * oacc[nf][3];
    }
    a10 += __shfl_xor_sync(0xffffffffu, a10, 1);
    a10 += __shfl_xor_sync(0xffffffffu, a10, 2);
    a20 += __shfl_xor_sync(0xffffffffu, a20, 1);
    a20 += __shfl_xor_sync(0xffffffffu, a20, 2);
    a11 += __shfl_xor_sync(0xffffffffu, a11, 1);
    a11 += __shfl_xor_sync(0xffffffffu, a11, 2);
    a21 += __shfl_xor_sync(0xffffffffu, a21, 1);
    a21 += __shfl_xor_sync(0xffffffffu, a21, 2);
    if (l4 == 0) {
        red1[r0l][nh] = a10; red2[r0l][nh] = a20;
        red1[r1l][nh] = a11; red2[r1l][nh] = a21;
    }
    __syncthreads();

    float mu0  = (red1[r0l][0] + red1[r0l][1]) * (1.0f / DHEAD);
    float var0 = (red2[r0l][0] + red2[r0l][1]) * (1.0f / DHEAD) - mu0 * mu0;
    float rstd0 = rsqrtf(var0 + EPS);
    float mu1  = (red1[r1l][0] + red1[r1l][1]) * (1.0f / DHEAD);
    float var1 = (red2[r1l][0] + red2[r1l][1]) * (1.0f / DHEAD) - mu1 * mu1;
    float rstd1 = rsqrtf(var1 + EPS);

#pragma unroll
    for (int nf = 0; nf < 8; nf++) {
        int col = nh * 64 + nf * 8 + 2 * l4;
        float w0 = lnsc[h * DHEAD + col];
        float w1 = lnsc[h * DHEAD + col + 1];
        float2 o0, o1;
        o0.x = (oacc[nf][0] - mu0) * rstd0 * w0;
        o0.y = (oacc[nf][1] - mu0) * rstd0 * w1;
        o1.x = (oacc[nf][2] - mu1) * rstd1 * w0;
        o1.y = (oacc[nf][3] - mu1) * rstd1 * w1;
        *(float2*)(out + (size_t)(i0 + r0l) * E_DIM + h * DHEAD + col) = o0;
        *(float2*)(out + (size_t)(i0 + r1l) * E_DIM + h * DHEAD + col) = o1;
    }
}

// ---------------- launch --------------------------------------------------------
extern "C" void kernel_launch(void* const* d_in, const int* in_sizes, int n_in,
                              void* d_out, int out_size)
{
    const float* q    = (const float*)d_in[0];
    const float* k    = (const float*)d_in[1];
    const float* v    = (const float*)d_in[2];
    const float* Wi   = (const float*)d_in[3];
    const float* bi   = (const float*)d_in[4];
    const float* Wf   = (const float*)d_in[5];
    const float* bf   = (const float*)d_in[6];
    const float* lnsc = (const float*)d_in[7];
    float* out = (float*)d_out;

    cudaFuncSetAttribute(mlstm_main_kernel,
                         cudaFuncAttributeMaxDynamicSharedMemorySize, SMEM_BYTES);
    cudaFuncSetAttribute(gates_kernel,
                         cudaFuncAttributeMaxDynamicSharedMemorySize, 16 * 1024 * 4);

    dim3 pgrid(2048, 3);
    preconvert_kernel<<<pgrid, 256>>>(q, k, v);
    dim3 ggrid(64, 3);
    gates_kernel<<<ggrid, 256, 16 * 1024 * 4>>>(q, k, v, Wi, Wf);
    scan_kernel<<<NHEAD, 256>>>(bi, bf);
    dim3 grid(32, NHEAD);
    mlstm_main_kernel<<<grid, 256, SMEM_BYTES>>>(lnsc, out);
}